// round 2
// baseline (speedup 1.0000x reference)
#include <cuda_runtime.h>
#include <cstdint>
#include <cstddef>

#define B_   4
#define NP_  512
#define NC_  256
#define E_   128
#define C_   32
#define Q_   (NP_*NC_)          // 131072
#define CQ_  (C_*Q_)            // 4194304 per batch
#define NB_  20

// ---------------- scratch (device globals; no allocation) ----------------
__device__ float g_disb[(size_t)B_*NP_*NC_*C_];   // natural [b][np][nc][cc] flat
__device__ float g_zc  [(size_t)B_*C_*NC_*NP_];   // [b][cc][nc][np]
__device__ float g_lig [(size_t)B_*C_*NC_*E_];    // [b][cc][nc][e]
__device__ float g_acc [8];                       // [0..3]=energy, [4..7]=prmsd
__device__ int   g_mtype;                         // 0=u8, 1=i32, 2=f32

// ---------------- K-1: detect z_mask dtype --------------------------------
__global__ void k_detect(const unsigned int* __restrict__ m)
{
    if (threadIdx.x == 0) {
        bool alli = true, allf = true;
        for (int i = 0; i < 64; i++) {
            unsigned int v = m[i * 97];          // < 6208 dwords, safe for u8 case
            if (!(v == 0u || v == 1u))           alli = false;
            if (!(v == 0u || v == 0x3F800000u))  allf = false;
        }
        g_mtype = alli ? 1 : (allf ? 2 : 0);
    }
}

__device__ __forceinline__ bool mask_at(const void* zm, size_t idx, int mt)
{
    if (mt == 1) return ((const int*)zm)[idx] != 0;
    if (mt == 2) return ((const float*)zm)[idx] != 0.f;
    return ((const unsigned char*)zm)[idx] != 0;
}

// ---------------- K0: distance-bucket bias --------------------------------
__global__ void __launch_bounds__(256) k_disb(const float* __restrict__ cand,
                                              const float* __restrict__ Wd,
                                              const float* __restrict__ bd)
{
    __shared__ float sWd[NB_*32];
    __shared__ float sBd[32];
    int t = threadIdx.x;
    for (int i = t; i < NB_*32; i += 256) sWd[i] = Wd[i];
    if (t < 32) sBd[t] = bd[t];
    __syncthreads();

    int w = t >> 5, lane = t & 31;
    int s = blockIdx.x * 8 + w;              // s = (b*NP+np)*NC+nc
    float x = cand[s];

    float ev = 0.f;
    if (lane < NB_) {
        float v  = (float)(lane + 1) * (15.0f / 21.0f);   // linspace(0,15,22)[1:-1]
        float d  = (x - v) * (21.0f / 15.0f);             // /step
        float a  = d + 1.0f;
        float c2 = 1.0f - d;
        if (a > 0.f && c2 > 0.f)
            ev = 8.4335730689f * __expf(-__fdividef(1.f, a) - __fdividef(1.f, c2));
    }
    float acc = sBd[lane];
#pragma unroll
    for (int k = 0; k < NB_; k++) {
        float ek = __shfl_sync(0xffffffffu, ev, k);
        acc = fmaf(ek, sWd[k*32 + lane], acc);
    }
    g_disb[(size_t)s * 32 + lane] = acc;

    if (blockIdx.x == 0 && t < 8) g_acc[t] = 0.f;   // stream-ordered before k_main
}

// ---------------- K1: fused zlin GEMM + softmax + bias + mask + energy ----
__global__ void __launch_bounds__(256) k_main(const float* __restrict__ z,
                                              const void* __restrict__ zmask,
                                              const float* __restrict__ Wlin,
                                              const float* __restrict__ blin,
                                              const float* __restrict__ We,  const float* __restrict__ be,
                                              const float* __restrict__ Wg,  const float* __restrict__ bg,
                                              const float* __restrict__ Wep, const float* __restrict__ bep,
                                              const float* __restrict__ Wgp, const float* __restrict__ bgp)
{
    extern __shared__ float smem[];
    float* sW   = smem;              // 4096  : W_lin [128][32]
    float* sT   = sW  + 4096;        // 16896 : tile [512][33]
    float* sZ   = sT  + 16896;       // 1024  : 8 warps x 128 z-row staging
    float* sWE  = sZ  + 1024;        // 32
    float* sWG  = sWE + 32;          // 32
    float* sWEP = sWG + 32;          // 32
    float* sWGP = sWEP+ 32;          // 32
    float* sRed = sWGP+ 32;          // 16

    int t    = threadIdx.x;
    int b    = blockIdx.x >> 8;
    int nc   = blockIdx.x & 255;
    int w    = t >> 5, lane = t & 31;
    int mt   = g_mtype;

    for (int i = t; i < 4096; i += 256) sW[i] = Wlin[i];
    if (t < 32) { sWE[t] = We[t]; sWG[t] = Wg[t]; sWEP[t] = Wep[t]; sWGP[t] = Wgp[t]; }
    __syncthreads();

    float bl = blin[lane];

    // ---- phase 1: z @ W_lin + b_lin, rows np = w + 8*r ----
    const size_t rowstep = (size_t)8 * NC_ * E_;
    const float* zp = z + (((size_t)b * NP_ + w) * NC_ + nc) * E_;
    float4  zr  = reinterpret_cast<const float4*>(zp)[lane];
    float4* sZ4 = reinterpret_cast<float4*>(sZ + w * 128);

    for (int r = 0; r < 64; r++) {
        sZ4[lane] = zr;
        __syncwarp();
        const float* znext = zp + rowstep;
        if (r < 63) zr = reinterpret_cast<const float4*>(znext)[lane];
        zp = znext;

        float acc = 0.f;
#pragma unroll
        for (int k4 = 0; k4 < 32; k4++) {
            float4 v = sZ4[k4];
            acc = fmaf(v.x, sW[(k4*4+0)*32 + lane], acc);
            acc = fmaf(v.y, sW[(k4*4+1)*32 + lane], acc);
            acc = fmaf(v.z, sW[(k4*4+2)*32 + lane], acc);
            acc = fmaf(v.w, sW[(k4*4+3)*32 + lane], acc);
        }
        int np = w + 8 * r;
        sT[np * 33 + lane] = acc + bl;
        __syncwarp();
    }
    __syncthreads();

    // ---- phase 2: softmax over np, + dis_bias, weird-reshape mask, write g_zc ----
    for (int cr = w; cr < 32; cr += 8) {
        float vv[16];
        float mx = -3.0e38f;
#pragma unroll
        for (int i = 0; i < 16; i++) { vv[i] = sT[(lane + 32*i)*33 + cr]; mx = fmaxf(mx, vv[i]); }
#pragma unroll
        for (int off = 16; off >= 1; off >>= 1) mx = fmaxf(mx, __shfl_xor_sync(0xffffffffu, mx, off));
        float sum = 0.f;
#pragma unroll
        for (int i = 0; i < 16; i++) { vv[i] = __expf(vv[i] - mx); sum += vv[i]; }
#pragma unroll
        for (int off = 16; off >= 1; off >>= 1) sum += __shfl_xor_sync(0xffffffffu, sum, off);
        float inv = 1.0f / sum;

        size_t gb = (size_t)b * CQ_ + (size_t)(cr * NC_ + nc) * NP_;
        size_t mb = (size_t)(cr & 3) * Q_ + (size_t)nc * NP_;
#pragma unroll
        for (int i = 0; i < 16; i++) {
            int np = lane + 32 * i;
            float val = fmaf(vv[i], inv, g_disb[gb + np]);
            if (mask_at(zmask, mb + np, mt)) val = 1e-9f;
            g_zc[gb + np] = val;
            sT[np * 33 + cr] = val;
        }
    }
    __syncthreads();

    // ---- phase 3: gated energy heads, accumulate per-b ----
    float bE = be[0], bG = bg[0], bEp = bep[0], bGp = bgp[0];
    float se = 0.f, sp = 0.f;
    for (int np = t; np < NP_; np += 256) {
        float ea = 0.f, ga = 0.f, e2 = 0.f, g2 = 0.f;
#pragma unroll
        for (int cc = 0; cc < 32; cc++) {
            float v = sT[np * 33 + cc];
            ea = fmaf(v, sWE[cc],  ea);
            ga = fmaf(v, sWG[cc],  ga);
            e2 = fmaf(v, sWEP[cc], e2);
            g2 = fmaf(v, sWGP[cc], g2);
        }
        if (mask_at(zmask, ((size_t)b * NP_ + np) * NC_ + nc, mt)) {
            se += (ea + bE)  / (1.f + __expf(-(ga + bG)));
            sp += (e2 + bEp) / (1.f + __expf(-(g2 + bGp)));
        }
    }
#pragma unroll
    for (int off = 16; off >= 1; off >>= 1) {
        se += __shfl_xor_sync(0xffffffffu, se, off);
        sp += __shfl_xor_sync(0xffffffffu, sp, off);
    }
    if (lane == 0) { sRed[w] = se; sRed[8 + w] = sp; }
    __syncthreads();
    if (t == 0) {
        float a = 0.f, p2 = 0.f;
        for (int i = 0; i < 8; i++) { a += sRed[i]; p2 += sRed[8 + i]; }
        atomicAdd(&g_acc[b],     a);
        atomicAdd(&g_acc[4 + b], p2);
    }
}

// ---------------- K4: lig[b,cc,nc,e] = sum_np zc * pocket -----------------
__global__ void __launch_bounds__(256) k_lig(const float* __restrict__ pocket)
{
    __shared__ float sA[64 * 32];
    __shared__ float sB[32 * 128];
    int t  = threadIdx.x;
    int mt = blockIdx.x;
    int b  = blockIdx.y;
    int tx = t & 31, ty = t >> 5;

    const float* Ab = g_zc + (size_t)b * C_ * NC_ * NP_ + (size_t)mt * 64 * NP_;
    const float* Bb = pocket + (size_t)b * NP_ * E_;

    float4 acc[8];
#pragma unroll
    for (int i = 0; i < 8; i++) acc[i] = make_float4(0.f, 0.f, 0.f, 0.f);

    for (int k0 = 0; k0 < NP_; k0 += 32) {
#pragma unroll
        for (int u = 0; u < 2; u++) {                 // A tile: 64x32
            int idx = t + u * 256; int i = idx >> 3; int f4 = idx & 7;
            reinterpret_cast<float4*>(sA)[i*8 + f4] =
                reinterpret_cast<const float4*>(Ab + (size_t)i * NP_ + k0)[f4];
        }
#pragma unroll
        for (int u = 0; u < 4; u++) {                 // B tile: 32x128
            int idx = t + u * 256; int kk = idx >> 5; int c4 = idx & 31;
            reinterpret_cast<float4*>(sB)[kk*32 + c4] =
                reinterpret_cast<const float4*>(Bb + (size_t)(k0 + kk) * E_)[c4];
        }
        __syncthreads();
#pragma unroll 4
        for (int kk = 0; kk < 32; kk++) {
            float4 bv = reinterpret_cast<const float4*>(sB)[kk*32 + tx];
#pragma unroll
            for (int i8 = 0; i8 < 8; i8++) {
                float a = sA[(ty + 8*i8)*32 + kk];
                acc[i8].x = fmaf(a, bv.x, acc[i8].x);
                acc[i8].y = fmaf(a, bv.y, acc[i8].y);
                acc[i8].z = fmaf(a, bv.z, acc[i8].z);
                acc[i8].w = fmaf(a, bv.w, acc[i8].w);
            }
        }
        __syncthreads();
    }
    float* Ob = g_lig + ((size_t)b * C_ * NC_ + (size_t)mt * 64) * E_;
#pragma unroll
    for (int i8 = 0; i8 < 8; i8++)
        reinterpret_cast<float4*>(Ob + (size_t)(ty + 8*i8) * E_)[tx] = acc[i8];
}

// ---------------- K5: ligand_rep = lig2 @ W_out + b_out -------------------
__global__ void __launch_bounds__(256) k_out(const float* __restrict__ Wout,
                                             const float* __restrict__ bout,
                                             float* __restrict__ out)
{
    __shared__ float sA[16 * 128];
    __shared__ float sB[128 * 64];
    int t  = threadIdx.x;
    int tx = t & 31, ty = t >> 5;
    int eo0 = blockIdx.x * 64;
    int r0  = blockIdx.y * 16;
    int b   = r0 >> 8;
    int nc0 = r0 & 255;

    const size_t NCE = (size_t)NC_ * E_;
    const float* Lb = g_lig + (size_t)b * C_ * NCE + (size_t)nc0 * E_;

    float2 acc0 = make_float2(0.f, 0.f), acc1 = make_float2(0.f, 0.f);

    for (int cc = 0; cc < 32; cc++) {
#pragma unroll
        for (int u = 0; u < 2; u++) {                 // A: 16x128 (one cc chunk)
            int idx = t + u * 256; int i = idx >> 5; int f4 = idx & 31;
            reinterpret_cast<float4*>(sA)[i*32 + f4] =
                reinterpret_cast<const float4*>(Lb + (size_t)cc * NCE + (size_t)i * E_)[f4];
        }
#pragma unroll
        for (int u = 0; u < 8; u++) {                 // B: 128x64 slice of W_out
            int idx = t + u * 256; int kk = idx >> 4; int c4 = idx & 15;
            reinterpret_cast<float4*>(sB)[kk*16 + c4] =
                reinterpret_cast<const float4*>(Wout + (size_t)(cc*128 + kk) * E_ + eo0)[c4];
        }
        __syncthreads();
#pragma unroll 8
        for (int kk = 0; kk < 128; kk++) {
            float a0 = sA[ty * 128 + kk];
            float a1 = sA[(ty + 8) * 128 + kk];
            float2 bv = reinterpret_cast<const float2*>(sB)[kk*32 + tx];
            acc0.x = fmaf(a0, bv.x, acc0.x);
            acc0.y = fmaf(a0, bv.y, acc0.y);
            acc1.x = fmaf(a1, bv.x, acc1.x);
            acc1.y = fmaf(a1, bv.y, acc1.y);
        }
        __syncthreads();
    }
    int eo = eo0 + 2 * tx;
    float2 bo = *reinterpret_cast<const float2*>(bout + eo);
    acc0.x += bo.x; acc0.y += bo.y;
    acc1.x += bo.x; acc1.y += bo.y;
    *reinterpret_cast<float2*>(out + (size_t)(r0 + ty)     * E_ + eo) = acc0;
    *reinterpret_cast<float2*>(out + (size_t)(r0 + ty + 8) * E_ + eo) = acc1;
}

// ---------------- K6: finalize affinity / prmsd ---------------------------
__global__ void k_fin(const float* __restrict__ bias,
                      const float* __restrict__ bias_p,
                      float* __restrict__ out)
{
    int t = threadIdx.x;
    if (t < 4) {
        float a = bias[0] + g_acc[t];
        out[131072 + t] = (a > 0.f) ? a : 0.01f * a;
        float p = bias_p[0] + g_acc[4 + t];
        out[131076 + t] = (p > 0.f) ? p : 0.01f * p;
    }
}

// ---------------- launch --------------------------------------------------
extern "C" void kernel_launch(void* const* d_in, const int* in_sizes, int n_in,
                              void* d_out, int out_size)
{
    const float* z      = (const float*)d_in[0];
    const void*  zmask  = d_in[1];
    const float* pocket = (const float*)d_in[2];
    const float* cand   = (const float*)d_in[3];
    const float* Wlin   = (const float*)d_in[4];
    const float* blin   = (const float*)d_in[5];
    const float* Wdis   = (const float*)d_in[6];
    const float* bdis   = (const float*)d_in[7];
    const float* We     = (const float*)d_in[8];
    const float* be     = (const float*)d_in[9];
    const float* Wg     = (const float*)d_in[10];
    const float* bg     = (const float*)d_in[11];
    const float* bias   = (const float*)d_in[12];
    const float* Wep    = (const float*)d_in[13];
    const float* bep    = (const float*)d_in[14];
    const float* Wgp    = (const float*)d_in[15];
    const float* bgp    = (const float*)d_in[16];
    const float* biasp  = (const float*)d_in[17];
    const float* Wout   = (const float*)d_in[18];
    const float* bout   = (const float*)d_in[19];
    float* out = (float*)d_out;

    const int K1_SMEM = (4096 + 16896 + 1024 + 128 + 16) * 4;   // 88640 bytes
    cudaFuncSetAttribute(k_main, cudaFuncAttributeMaxDynamicSharedMemorySize, K1_SMEM);

    k_detect<<<1, 32>>>((const unsigned int*)zmask);
    k_disb<<<(B_*NP_*NC_)/8, 256>>>(cand, Wdis, bdis);
    k_main<<<B_*NC_, 256, K1_SMEM>>>(z, zmask, Wlin, blin, We, be, Wg, bg, Wep, bep, Wgp, bgp);
    k_lig<<<dim3((C_*NC_)/64, B_), 256>>>(pocket);
    k_out<<<dim3(E_/64, (B_*NC_)/16), 256>>>(Wout, bout, out);
    k_fin<<<1, 32>>>(bias, biasp, out);
}

// round 4
// speedup vs baseline: 1.1115x; 1.1115x over previous
#include <cuda_runtime.h>
#include <cstdint>
#include <cstddef>

#define B_   4
#define NP_  512
#define NC_  256
#define E_   128
#define C_   32
#define Q_   (NP_*NC_)          // 131072
#define CQ_  (C_*Q_)            // 4194304 per batch
#define NB_  20

typedef unsigned long long ull;

// ---------------- f32x2 packed helpers ------------------------------------
#define FMA2(d, a, b) asm("fma.rn.f32x2 %0, %1, %2, %0;" : "+l"(d) : "l"(a), "l"(b))
__device__ __forceinline__ ull pack2(float x, float y) {
    ull r; asm("mov.b64 %0, {%1, %2};" : "=l"(r) : "f"(x), "f"(y)); return r;
}
__device__ __forceinline__ void unpack2(float& x, float& y, ull v) {
    asm("mov.b64 {%0, %1}, %2;" : "=f"(x), "=f"(y) : "l"(v));
}

// ---------------- scratch (device globals; no allocation) ----------------
__device__ float g_disb[(size_t)B_*NP_*NC_*C_];   // natural [b][np][nc][cc] flat
__device__ float g_lig [(size_t)B_*C_*NC_*E_];    // [b][cc][nc][e]
__device__ float g_acc [8];                       // [0..3]=energy, [4..7]=prmsd
__device__ int   g_mtype;                         // 0=u8, 1=i32, 2=f32

// ---------------- K-1: detect z_mask dtype --------------------------------
__global__ void k_detect(const unsigned int* __restrict__ m)
{
    if (threadIdx.x == 0) {
        bool alli = true, allf = true;
        for (int i = 0; i < 64; i++) {
            unsigned int v = m[i * 97];
            if (!(v == 0u || v == 1u))           alli = false;
            if (!(v == 0u || v == 0x3F800000u))  allf = false;
        }
        g_mtype = alli ? 1 : (allf ? 2 : 0);
    }
}

__device__ __forceinline__ bool mask_at(const void* zm, size_t idx, int mt)
{
    if (mt == 1) return ((const int*)zm)[idx] != 0;
    if (mt == 2) return ((const float*)zm)[idx] != 0.f;
    return ((const unsigned char*)zm)[idx] != 0;
}

// ---------------- K0: distance-bucket bias --------------------------------
__global__ void __launch_bounds__(256) k_disb(const float* __restrict__ cand,
                                              const float* __restrict__ Wd,
                                              const float* __restrict__ bd)
{
    __shared__ float sWd[NB_*32];
    __shared__ float sBd[32];
    int t = threadIdx.x;
    for (int i = t; i < NB_*32; i += 256) sWd[i] = Wd[i];
    if (t < 32) sBd[t] = bd[t];
    __syncthreads();

    int w = t >> 5, lane = t & 31;
    int s = blockIdx.x * 8 + w;              // s = (b*NP+np)*NC+nc
    float x = cand[s];

    float ev = 0.f;
    if (lane < NB_) {
        float v  = (float)(lane + 1) * (15.0f / 21.0f);
        float d  = (x - v) * (21.0f / 15.0f);
        float a  = d + 1.0f;
        float c2 = 1.0f - d;
        if (a > 0.f && c2 > 0.f)
            ev = 8.4335730689f * __expf(-__fdividef(1.f, a) - __fdividef(1.f, c2));
    }
    float acc = sBd[lane];
#pragma unroll
    for (int k = 0; k < NB_; k++) {
        float ek = __shfl_sync(0xffffffffu, ev, k);
        acc = fmaf(ek, sWd[k*32 + lane], acc);
    }
    g_disb[(size_t)s * 32 + lane] = acc;

    if (blockIdx.x == 0 && t < 8) g_acc[t] = 0.f;   // stream-ordered before k_main
}

// ---------------- K1: fused zlin GEMM + softmax + bias + mask + energy + lig
// One block per (b,nc). Dynamic smem layout (floats):
//   [0, 8320)       U: phase1 = sWt[32][132] (4224) + sZ[8w][4r][128] (4096)
//                      lig    = sP[64][128]  (8192)
//   [8320, 26752)   sT[512][36]
//   [26752, 26880)  sWE/sWG/sWEP/sWGP (4x32)
//   [26880, 26896)  sRed
__global__ void __launch_bounds__(256) k_main(const float* __restrict__ z,
                                              const void* __restrict__ zmask,
                                              const float* __restrict__ pocket,
                                              const float* __restrict__ Wlin,
                                              const float* __restrict__ blin,
                                              const float* __restrict__ We,  const float* __restrict__ be,
                                              const float* __restrict__ Wg,  const float* __restrict__ bg,
                                              const float* __restrict__ Wep, const float* __restrict__ bep,
                                              const float* __restrict__ Wgp, const float* __restrict__ bgp)
{
    extern __shared__ float smem[];
    float* sWt  = smem;                  // [32][132] transposed W_lin
    float* sZ   = smem + 4224;           // 8 warps x 4 rows x 128
    float* sP   = smem;                  // lig-phase pocket chunk (aliases sWt+sZ)
    float* sT   = smem + 8320;           // [512][36]
    float* sWE  = smem + 26752;
    float* sWG  = sWE + 32;
    float* sWEP = sWG + 32;
    float* sWGP = sWEP + 32;
    float* sRed = sWGP + 32;

    int t    = threadIdx.x;
    int b    = blockIdx.x >> 8;
    int nc   = blockIdx.x & 255;
    int w    = t >> 5, lane = t & 31;
    int mt   = g_mtype;

    // transpose-load W_lin: sWt[cc][k] = Wlin[k][cc]
    for (int i = t; i < 32*128; i += 256) {
        int cc = i & 31, k = i >> 5;
        sWt[cc*132 + k] = Wlin[k*32 + cc];
    }
    if (t < 32) { sWE[t] = We[t]; sWG[t] = Wg[t]; sWEP[t] = Wep[t]; sWGP[t] = Wgp[t]; }
    __syncthreads();

    float bl = blin[lane];

    // ---- phase 1: z @ W_lin + b_lin (packed f32x2, 4 rows per group) ----
    {
        const size_t rstep = (size_t)8 * NC_ * E_;      // np stride of 8
        const float* zp0 = z + (((size_t)b * NP_ + w) * NC_ + nc) * E_;
        const ulonglong2* wrow = reinterpret_cast<const ulonglong2*>(sWt + lane*132);

        float4 cur[4], nxt[4];
#pragma unroll
        for (int j = 0; j < 4; j++)
            cur[j] = reinterpret_cast<const float4*>(zp0 + (size_t)j * rstep)[lane];

        for (int g = 0; g < 16; g++) {
            if (g < 15) {
                const float* zn = zp0 + (size_t)(4*g + 4) * rstep;
#pragma unroll
                for (int j = 0; j < 4; j++)
                    nxt[j] = reinterpret_cast<const float4*>(zn + (size_t)j * rstep)[lane];
            }
#pragma unroll
            for (int j = 0; j < 4; j++)
                reinterpret_cast<float4*>(sZ + (w*4 + j)*128)[lane] = cur[j];
            __syncwarp();

            ull accA[4] = {0ull,0ull,0ull,0ull};
            ull accB[4] = {0ull,0ull,0ull,0ull};
#pragma unroll
            for (int k4 = 0; k4 < 32; k4++) {
                ulonglong2 wv = wrow[k4];
#pragma unroll
                for (int j = 0; j < 4; j++) {
                    ulonglong2 v = reinterpret_cast<const ulonglong2*>(sZ + (w*4 + j)*128)[k4];
                    FMA2(accA[j], v.x, wv.x);
                    FMA2(accB[j], v.y, wv.y);
                }
            }
#pragma unroll
            for (int j = 0; j < 4; j++) {
                float ax, ay, bx, by;
                unpack2(ax, ay, accA[j]);
                unpack2(bx, by, accB[j]);
                int np = w + 8 * (4*g + j);
                sT[np*36 + lane] = (ax + bx) + (ay + by) + bl;
                cur[j] = nxt[j];
            }
            __syncwarp();
        }
    }
    __syncthreads();

    // ---- phase 2: softmax over np, + dis_bias, weird-reshape mask ----
    for (int cr = w; cr < 32; cr += 8) {
        float vv[16];
        float mx = -3.0e38f;
#pragma unroll
        for (int i = 0; i < 16; i++) { vv[i] = sT[(lane + 32*i)*36 + cr]; mx = fmaxf(mx, vv[i]); }
#pragma unroll
        for (int off = 16; off >= 1; off >>= 1) mx = fmaxf(mx, __shfl_xor_sync(0xffffffffu, mx, off));
        float sum = 0.f;
#pragma unroll
        for (int i = 0; i < 16; i++) { vv[i] = __expf(vv[i] - mx); sum += vv[i]; }
#pragma unroll
        for (int off = 16; off >= 1; off >>= 1) sum += __shfl_xor_sync(0xffffffffu, sum, off);
        float inv = 1.0f / sum;

        size_t gb = (size_t)b * CQ_ + (size_t)(cr * NC_ + nc) * NP_;
        size_t mb = (size_t)(cr & 3) * Q_ + (size_t)nc * NP_;
#pragma unroll
        for (int i = 0; i < 16; i++) {
            int np = lane + 32 * i;
            float val = fmaf(vv[i], inv, g_disb[gb + np]);
            if (mask_at(zmask, mb + np, mt)) val = 1e-9f;
            sT[np*36 + cr] = val;
        }
    }
    __syncthreads();

    // ---- phase 3: gated energy heads, accumulate per-b ----
    {
        float bE = be[0], bG = bg[0], bEp = bep[0], bGp = bgp[0];
        float se = 0.f, sp = 0.f;
        for (int np = t; np < NP_; np += 256) {
            float ea = 0.f, ga = 0.f, e2 = 0.f, g2 = 0.f;
#pragma unroll
            for (int cc = 0; cc < 32; cc++) {
                float v = sT[np*36 + cc];
                ea = fmaf(v, sWE[cc],  ea);
                ga = fmaf(v, sWG[cc],  ga);
                e2 = fmaf(v, sWEP[cc], e2);
                g2 = fmaf(v, sWGP[cc], g2);
            }
            if (mask_at(zmask, ((size_t)b * NP_ + np) * NC_ + nc, mt)) {
                se += (ea + bE)  / (1.f + __expf(-(ga + bG)));
                sp += (e2 + bEp) / (1.f + __expf(-(g2 + bGp)));
            }
        }
#pragma unroll
        for (int off = 16; off >= 1; off >>= 1) {
            se += __shfl_xor_sync(0xffffffffu, se, off);
            sp += __shfl_xor_sync(0xffffffffu, sp, off);
        }
        if (lane == 0) { sRed[w] = se; sRed[8 + w] = sp; }
        __syncthreads();
        if (t == 0) {
            float a = 0.f, p2 = 0.f;
            for (int i = 0; i < 8; i++) { a += sRed[i]; p2 += sRed[8 + i]; }
            atomicAdd(&g_acc[b],     a);
            atomicAdd(&g_acc[4 + b], p2);
        }
    }

    // ---- phase 4 (fused lig): O[cc][e] = sum_np sT[np][cc] * pocket[b][np][e]
    // warp w owns cc = 4w..4w+3; lane owns e = 4*lane..4*lane+3
    {
        ull acc[8] = {0ull,0ull,0ull,0ull,0ull,0ull,0ull,0ull};
        for (int c0 = 0; c0 < 8; c0++) {
            __syncthreads();    // previous chunk fully consumed (also covers first-entry aliasing)
            const float4* Pg = reinterpret_cast<const float4*>(
                pocket + ((size_t)b * NP_ + c0 * 64) * E_);
            float4* sP4 = reinterpret_cast<float4*>(sP);
#pragma unroll
            for (int u = 0; u < 8; u++) sP4[t + 256*u] = Pg[t + 256*u];
            __syncthreads();

#pragma unroll 4
            for (int np = 0; np < 64; np++) {
                float4 a4 = *reinterpret_cast<const float4*>(&sT[(c0*64 + np)*36 + w*4]);
                ulonglong2 pv = *reinterpret_cast<const ulonglong2*>(&sP[np*128 + lane*4]);
                ull d0 = pack2(a4.x, a4.x);
                FMA2(acc[0], d0, pv.x); FMA2(acc[1], d0, pv.y);
                ull d1 = pack2(a4.y, a4.y);
                FMA2(acc[2], d1, pv.x); FMA2(acc[3], d1, pv.y);
                ull d2 = pack2(a4.z, a4.z);
                FMA2(acc[4], d2, pv.x); FMA2(acc[5], d2, pv.y);
                ull d3 = pack2(a4.w, a4.w);
                FMA2(acc[6], d3, pv.x); FMA2(acc[7], d3, pv.y);
            }
        }
#pragma unroll
        for (int j = 0; j < 4; j++) {
            float4 o;
            unpack2(o.x, o.y, acc[2*j]);
            unpack2(o.z, o.w, acc[2*j + 1]);
            int cc = w*4 + j;
            reinterpret_cast<float4*>(
                g_lig + (((size_t)b * C_ + cc) * NC_ + nc) * E_)[lane] = o;
        }
    }
}

// ---------------- K5: ligand_rep = lig2 @ W_out + b_out -------------------
__global__ void __launch_bounds__(256) k_out(const float* __restrict__ Wout,
                                             const float* __restrict__ bout,
                                             float* __restrict__ out)
{
    __shared__ float sA[16 * 128];
    __shared__ float sB[128 * 64];
    int t  = threadIdx.x;
    int tx = t & 31, ty = t >> 5;
    int eo0 = blockIdx.x * 64;
    int r0  = blockIdx.y * 16;
    int b   = r0 >> 8;
    int nc0 = r0 & 255;

    const size_t NCE = (size_t)NC_ * E_;
    const float* Lb = g_lig + (size_t)b * C_ * NCE + (size_t)nc0 * E_;

    float2 acc0 = make_float2(0.f, 0.f), acc1 = make_float2(0.f, 0.f);

    for (int cc = 0; cc < 32; cc++) {
#pragma unroll
        for (int u = 0; u < 2; u++) {
            int idx = t + u * 256; int i = idx >> 5; int f4 = idx & 31;
            reinterpret_cast<float4*>(sA)[i*32 + f4] =
                reinterpret_cast<const float4*>(Lb + (size_t)cc * NCE + (size_t)i * E_)[f4];
        }
#pragma unroll
        for (int u = 0; u < 8; u++) {
            int idx = t + u * 256; int kk = idx >> 4; int c4 = idx & 15;
            reinterpret_cast<float4*>(sB)[kk*16 + c4] =
                reinterpret_cast<const float4*>(Wout + (size_t)(cc*128 + kk) * E_ + eo0)[c4];
        }
        __syncthreads();
#pragma unroll 8
        for (int kk = 0; kk < 128; kk++) {
            float a0 = sA[ty * 128 + kk];
            float a1 = sA[(ty + 8) * 128 + kk];
            float2 bv = reinterpret_cast<const float2*>(sB)[kk*32 + tx];
            acc0.x = fmaf(a0, bv.x, acc0.x);
            acc0.y = fmaf(a0, bv.y, acc0.y);
            acc1.x = fmaf(a1, bv.x, acc1.x);
            acc1.y = fmaf(a1, bv.y, acc1.y);
        }
        __syncthreads();
    }
    int eo = eo0 + 2 * tx;
    float2 bo = *reinterpret_cast<const float2*>(bout + eo);
    acc0.x += bo.x; acc0.y += bo.y;
    acc1.x += bo.x; acc1.y += bo.y;
    *reinterpret_cast<float2*>(out + (size_t)(r0 + ty)     * E_ + eo) = acc0;
    *reinterpret_cast<float2*>(out + (size_t)(r0 + ty + 8) * E_ + eo) = acc1;
}

// ---------------- K6: finalize affinity / prmsd ---------------------------
__global__ void k_fin(const float* __restrict__ bias,
                      const float* __restrict__ bias_p,
                      float* __restrict__ out)
{
    int t = threadIdx.x;
    if (t < 4) {
        float a = bias[0] + g_acc[t];
        out[131072 + t] = (a > 0.f) ? a : 0.01f * a;
        float p = bias_p[0] + g_acc[4 + t];
        out[131076 + t] = (p > 0.f) ? p : 0.01f * p;
    }
}

// ---------------- launch --------------------------------------------------
extern "C" void kernel_launch(void* const* d_in, const int* in_sizes, int n_in,
                              void* d_out, int out_size)
{
    const float* z      = (const float*)d_in[0];
    const void*  zmask  = d_in[1];
    const float* pocket = (const float*)d_in[2];
    const float* cand   = (const float*)d_in[3];
    const float* Wlin   = (const float*)d_in[4];
    const float* blin   = (const float*)d_in[5];
    const float* Wdis   = (const float*)d_in[6];
    const float* bdis   = (const float*)d_in[7];
    const float* We     = (const float*)d_in[8];
    const float* be     = (const float*)d_in[9];
    const float* Wg     = (const float*)d_in[10];
    const float* bg     = (const float*)d_in[11];
    const float* bias   = (const float*)d_in[12];
    const float* Wep    = (const float*)d_in[13];
    const float* bep    = (const float*)d_in[14];
    const float* Wgp    = (const float*)d_in[15];
    const float* bgp    = (const float*)d_in[16];
    const float* biasp  = (const float*)d_in[17];
    const float* Wout   = (const float*)d_in[18];
    const float* bout   = (const float*)d_in[19];
    float* out = (float*)d_out;

    const int K1_SMEM = 26896 * 4;   // 107584 bytes
    cudaFuncSetAttribute(k_main, cudaFuncAttributeMaxDynamicSharedMemorySize, K1_SMEM);

    k_detect<<<1, 32>>>((const unsigned int*)zmask);
    k_disb<<<(B_*NP_*NC_)/8, 256>>>(cand, Wdis, bdis);
    k_main<<<B_*NC_, 256, K1_SMEM>>>(z, zmask, pocket, Wlin, blin,
                                     We, be, Wg, bg, Wep, bep, Wgp, bgp);
    k_out<<<dim3(E_/64, (B_*NC_)/16), 256>>>(Wout, bout, out);
    k_fin<<<1, 32>>>(bias, biasp, out);
}

// round 5
// speedup vs baseline: 1.8226x; 1.6398x over previous
#include <cuda_runtime.h>
#include <cstdint>
#include <cstddef>

#define B_   4
#define NP_  512
#define NC_  256
#define E_   128
#define C_   32
#define Q_   (NP_*NC_)          // 131072
#define CQ_  (C_*Q_)            // 4194304 per batch
#define NB_  20

typedef unsigned long long ull;

// ---------------- f32x2 packed helpers ------------------------------------
#define FMA2(d, a, b) asm("fma.rn.f32x2 %0, %1, %2, %0;" : "+l"(d) : "l"(a), "l"(b))
__device__ __forceinline__ ull pack2(float x, float y) {
    ull r; asm("mov.b64 %0, {%1, %2};" : "=l"(r) : "f"(x), "f"(y)); return r;
}
__device__ __forceinline__ void unpack2(float& x, float& y, ull v) {
    asm("mov.b64 {%0, %1}, %2;" : "=f"(x), "=f"(y) : "l"(v));
}

// ---------------- scratch (device globals; no allocation) ----------------
__device__ float g_disb[(size_t)B_*NP_*NC_*C_];   // natural [b][np][nc][cc] flat
__device__ float g_lig [(size_t)B_*C_*NC_*E_];    // [b][cc][nc][e]
__device__ float g_part[(size_t)8*1024*128];      // split-K partials for k_out
__device__ float g_acc [8];                       // [0..3]=energy, [4..7]=prmsd
__device__ int   g_mtype;                         // 0=u8, 1=i32, 2=f32

// ---------------- K-1: detect z_mask dtype --------------------------------
__global__ void k_detect(const unsigned int* __restrict__ m)
{
    if (threadIdx.x == 0) {
        bool alli = true, allf = true;
        for (int i = 0; i < 64; i++) {
            unsigned int v = m[i * 97];
            if (!(v == 0u || v == 1u))           alli = false;
            if (!(v == 0u || v == 0x3F800000u))  allf = false;
        }
        g_mtype = alli ? 1 : (allf ? 2 : 0);
    }
}

__device__ __forceinline__ bool mask_at(const void* zm, size_t idx, int mt)
{
    if (mt == 1) return ((const int*)zm)[idx] != 0;
    if (mt == 2) return ((const float*)zm)[idx] != 0.f;
    return ((const unsigned char*)zm)[idx] != 0;
}

// ---------------- K0: distance-bucket bias --------------------------------
__global__ void __launch_bounds__(256) k_disb(const float* __restrict__ cand,
                                              const float* __restrict__ Wd,
                                              const float* __restrict__ bd)
{
    __shared__ float sWd[NB_*32];
    __shared__ float sBd[32];
    int t = threadIdx.x;
    for (int i = t; i < NB_*32; i += 256) sWd[i] = Wd[i];
    if (t < 32) sBd[t] = bd[t];
    __syncthreads();

    int w = t >> 5, lane = t & 31;
    int s = blockIdx.x * 8 + w;              // s = (b*NP+np)*NC+nc
    float x = cand[s];

    float ev = 0.f;
    if (lane < NB_) {
        float v  = (float)(lane + 1) * (15.0f / 21.0f);
        float d  = (x - v) * (21.0f / 15.0f);
        float a  = d + 1.0f;
        float c2 = 1.0f - d;
        if (a > 0.f && c2 > 0.f)
            ev = 8.4335730689f * __expf(-__fdividef(1.f, a) - __fdividef(1.f, c2));
    }
    float acc = sBd[lane];
#pragma unroll
    for (int k = 0; k < NB_; k++) {
        float ek = __shfl_sync(0xffffffffu, ev, k);
        acc = fmaf(ek, sWd[k*32 + lane], acc);
    }
    g_disb[(size_t)s * 32 + lane] = acc;

    if (blockIdx.x == 0 && t < 8) g_acc[t] = 0.f;   // stream-ordered before k_main
}

// ---------------- K1: fused zlin GEMM + softmax + bias + mask + energy + lig
// 512 threads (16 warps). Dynamic smem layout (floats):
//   [0, 12416)      U: phase1 = sWt[32][132] (4224) + sZ[16w][4r][128] (8192)
//                      lig    = sP[64][128]  (8192)
//   [12416, 29824)  sT[512][34]
//   [29824, 29952)  sWE/sWG/sWEP/sWGP (4x32)
//   [29952, 29984)  sRed[32]
__global__ void __launch_bounds__(512) k_main(const float* __restrict__ z,
                                              const void* __restrict__ zmask,
                                              const float* __restrict__ pocket,
                                              const float* __restrict__ Wlin,
                                              const float* __restrict__ blin,
                                              const float* __restrict__ We,  const float* __restrict__ be,
                                              const float* __restrict__ Wg,  const float* __restrict__ bg,
                                              const float* __restrict__ Wep, const float* __restrict__ bep,
                                              const float* __restrict__ Wgp, const float* __restrict__ bgp)
{
    extern __shared__ float smem[];
    float* sWt  = smem;                  // [32][132] transposed W_lin
    float* sZ   = smem + 4224;           // 16 warps x 4 rows x 128
    float* sP   = smem;                  // lig-phase pocket chunk (aliases sWt+sZ)
    float* sT   = smem + 12416;          // [512][34]
    float* sWE  = smem + 29824;
    float* sWG  = sWE + 32;
    float* sWEP = sWG + 32;
    float* sWGP = sWEP + 32;
    float* sRed = sWGP + 32;             // [32]

    int t    = threadIdx.x;
    int b    = blockIdx.x >> 8;
    int nc   = blockIdx.x & 255;
    int w    = t >> 5, lane = t & 31;
    int mt   = g_mtype;

    // transpose-load W_lin: sWt[cc][k] = Wlin[k][cc]
    for (int i = t; i < 32*128; i += 512) {
        int cc = i & 31, k = i >> 5;
        sWt[cc*132 + k] = Wlin[k*32 + cc];
    }
    if (t < 32) { sWE[t] = We[t]; sWG[t] = Wg[t]; sWEP[t] = Wep[t]; sWGP[t] = Wgp[t]; }
    __syncthreads();

    float bl = blin[lane];

    // ---- phase 1: z @ W_lin + b_lin (packed f32x2, 16 warps x 4 rows) ----
    {
        const size_t rstep = (size_t)16 * NC_ * E_;     // np stride of 16
        const float* zp0 = z + (((size_t)b * NP_ + w) * NC_ + nc) * E_;
        const ulonglong2* wrow = reinterpret_cast<const ulonglong2*>(sWt + lane*132);

        float4 cur[4], nxt[4];
#pragma unroll
        for (int j = 0; j < 4; j++)
            cur[j] = reinterpret_cast<const float4*>(zp0 + (size_t)j * rstep)[lane];

        for (int g = 0; g < 8; g++) {
            if (g < 7) {
                const float* zn = zp0 + (size_t)(4*g + 4) * rstep;
#pragma unroll
                for (int j = 0; j < 4; j++)
                    nxt[j] = reinterpret_cast<const float4*>(zn + (size_t)j * rstep)[lane];
            }
#pragma unroll
            for (int j = 0; j < 4; j++)
                reinterpret_cast<float4*>(sZ + (w*4 + j)*128)[lane] = cur[j];
            __syncwarp();

            ull accA[4] = {0ull,0ull,0ull,0ull};
            ull accB[4] = {0ull,0ull,0ull,0ull};
#pragma unroll
            for (int k4 = 0; k4 < 32; k4++) {
                ulonglong2 wv = wrow[k4];
#pragma unroll
                for (int j = 0; j < 4; j++) {
                    ulonglong2 v = reinterpret_cast<const ulonglong2*>(sZ + (w*4 + j)*128)[k4];
                    FMA2(accA[j], v.x, wv.x);
                    FMA2(accB[j], v.y, wv.y);
                }
            }
#pragma unroll
            for (int j = 0; j < 4; j++) {
                float ax, ay, bx, by;
                unpack2(ax, ay, accA[j]);
                unpack2(bx, by, accB[j]);
                int np = w + 16 * (4*g + j);
                sT[np*34 + lane] = (ax + bx) + (ay + by) + bl;
                cur[j] = nxt[j];
            }
            __syncwarp();
        }
    }
    __syncthreads();

    // ---- phase 2: softmax over np, + dis_bias, weird-reshape mask ----
    for (int cr = w; cr < 32; cr += 16) {
        float vv[16];
        float mx = -3.0e38f;
#pragma unroll
        for (int i = 0; i < 16; i++) { vv[i] = sT[(lane + 32*i)*34 + cr]; mx = fmaxf(mx, vv[i]); }
#pragma unroll
        for (int off = 16; off >= 1; off >>= 1) mx = fmaxf(mx, __shfl_xor_sync(0xffffffffu, mx, off));
        float sum = 0.f;
#pragma unroll
        for (int i = 0; i < 16; i++) { vv[i] = __expf(vv[i] - mx); sum += vv[i]; }
#pragma unroll
        for (int off = 16; off >= 1; off >>= 1) sum += __shfl_xor_sync(0xffffffffu, sum, off);
        float inv = 1.0f / sum;

        size_t gb = (size_t)b * CQ_ + (size_t)(cr * NC_ + nc) * NP_;
        size_t mb = (size_t)(cr & 3) * Q_ + (size_t)nc * NP_;
#pragma unroll
        for (int i = 0; i < 16; i++) {
            int np = lane + 32 * i;
            float val = fmaf(vv[i], inv, g_disb[gb + np]);
            if (mask_at(zmask, mb + np, mt)) val = 1e-9f;
            sT[np*34 + cr] = val;
        }
    }
    __syncthreads();

    // ---- phase 3: gated energy heads, accumulate per-b ----
    {
        float bE = be[0], bG = bg[0], bEp = bep[0], bGp = bgp[0];
        float se = 0.f, sp = 0.f;
        {
            int np = t;
            float ea = 0.f, ga = 0.f, e2 = 0.f, g2 = 0.f;
#pragma unroll
            for (int cc = 0; cc < 32; cc++) {
                float v = sT[np*34 + cc];
                ea = fmaf(v, sWE[cc],  ea);
                ga = fmaf(v, sWG[cc],  ga);
                e2 = fmaf(v, sWEP[cc], e2);
                g2 = fmaf(v, sWGP[cc], g2);
            }
            if (mask_at(zmask, ((size_t)b * NP_ + np) * NC_ + nc, mt)) {
                se = (ea + bE)  / (1.f + __expf(-(ga + bG)));
                sp = (e2 + bEp) / (1.f + __expf(-(g2 + bGp)));
            }
        }
#pragma unroll
        for (int off = 16; off >= 1; off >>= 1) {
            se += __shfl_xor_sync(0xffffffffu, se, off);
            sp += __shfl_xor_sync(0xffffffffu, sp, off);
        }
        if (lane == 0) { sRed[w] = se; sRed[16 + w] = sp; }
        __syncthreads();
        if (t == 0) {
            float a = 0.f, p2 = 0.f;
            for (int i = 0; i < 16; i++) { a += sRed[i]; p2 += sRed[16 + i]; }
            atomicAdd(&g_acc[b],     a);
            atomicAdd(&g_acc[4 + b], p2);
        }
    }

    // ---- phase 4 (fused lig): O[cc][e] = sum_np sT[np][cc] * pocket[b][np][e]
    // warp w owns cc = 2w, 2w+1; lane owns e = 4*lane..4*lane+3
    {
        ull acc[4] = {0ull,0ull,0ull,0ull};
        for (int c0 = 0; c0 < 8; c0++) {
            __syncthreads();    // previous chunk fully consumed (also covers first-entry aliasing)
            const float4* Pg = reinterpret_cast<const float4*>(
                pocket + ((size_t)b * NP_ + c0 * 64) * E_);
            float4* sP4 = reinterpret_cast<float4*>(sP);
#pragma unroll
            for (int u = 0; u < 4; u++) sP4[t + 512*u] = Pg[t + 512*u];
            __syncthreads();

#pragma unroll 4
            for (int np = 0; np < 64; np++) {
                float2 a2 = *reinterpret_cast<const float2*>(&sT[(c0*64 + np)*34 + w*2]);
                ulonglong2 pv = *reinterpret_cast<const ulonglong2*>(&sP[np*128 + lane*4]);
                ull d0 = pack2(a2.x, a2.x);
                FMA2(acc[0], d0, pv.x); FMA2(acc[1], d0, pv.y);
                ull d1 = pack2(a2.y, a2.y);
                FMA2(acc[2], d1, pv.x); FMA2(acc[3], d1, pv.y);
            }
        }
#pragma unroll
        for (int j = 0; j < 2; j++) {
            float4 o;
            unpack2(o.x, o.y, acc[2*j]);
            unpack2(o.z, o.w, acc[2*j + 1]);
            int cc = w*2 + j;
            reinterpret_cast<float4*>(
                g_lig + (((size_t)b * C_ + cc) * NC_ + nc) * E_)[lane] = o;
        }
    }
}

// ---------------- K5: split-K GEMM partials -------------------------------
// grid (2 eo-halves, 16 M-tiles of 64 rows, 8 K-chunks of 4 cc), 256 threads.
// g_part[kc][row][eo] = sum over K-chunk of lig2[row][k] * Wout[k][eo]
__global__ void __launch_bounds__(256) k_out(const float* __restrict__ Wout)
{
    extern __shared__ float smem[];
    float* sAt = smem;            // [128 e][64 r]  (A transposed)
    float* sB  = smem + 8192;     // [128 e][64 eo]

    int t   = threadIdx.x;
    int eo0 = blockIdx.x * 64;
    int y   = blockIdx.y;         // M tile: rows y*64 .. y*64+63
    int kc  = blockIdx.z;         // cc group: 4*kc .. 4*kc+3
    int b   = y >> 2;
    int nc0 = (y & 3) * 64;
    int tx  = t & 15, ty = t >> 4;

    ull acc[4][2];
#pragma unroll
    for (int i = 0; i < 4; i++) { acc[i][0] = 0ull; acc[i][1] = 0ull; }

    for (int c = 0; c < 4; c++) {
        int ccg = kc*4 + c;
        const float* Ab = g_lig + (((size_t)b * C_ + ccg) * NC_ + nc0) * E_;
        const float* Bb = Wout + ((size_t)ccg * 128) * E_ + eo0;
        __syncthreads();
        // A: 64 rows x 128 e -> transposed sAt[e][r]
#pragma unroll
        for (int p = 0; p < 8; p++) {
            int idx = p*256 + t;            // 0..2047 float4s
            int r = idx & 63, e4 = idx >> 6;
            float4 v = reinterpret_cast<const float4*>(Ab + (size_t)r * E_)[e4];
            sAt[(4*e4+0)*64 + r] = v.x;
            sAt[(4*e4+1)*64 + r] = v.y;
            sAt[(4*e4+2)*64 + r] = v.z;
            sAt[(4*e4+3)*64 + r] = v.w;
        }
        // B: 128 e x 64 eo
#pragma unroll
        for (int p = 0; p < 8; p++) {
            int idx = p*256 + t;
            int c4 = idx & 15, e = idx >> 4;
            reinterpret_cast<float4*>(sB + e*64)[c4] =
                reinterpret_cast<const float4*>(Bb + (size_t)e * E_)[c4];
        }
        __syncthreads();
#pragma unroll 8
        for (int e = 0; e < 128; e++) {
            float4 av = *reinterpret_cast<const float4*>(&sAt[e*64 + 4*ty]);
            ulonglong2 bv = *reinterpret_cast<const ulonglong2*>(&sB[e*64 + 4*tx]);
            ull d0 = pack2(av.x, av.x);
            FMA2(acc[0][0], d0, bv.x); FMA2(acc[0][1], d0, bv.y);
            ull d1 = pack2(av.y, av.y);
            FMA2(acc[1][0], d1, bv.x); FMA2(acc[1][1], d1, bv.y);
            ull d2 = pack2(av.z, av.z);
            FMA2(acc[2][0], d2, bv.x); FMA2(acc[2][1], d2, bv.y);
            ull d3 = pack2(av.w, av.w);
            FMA2(acc[3][0], d3, bv.x); FMA2(acc[3][1], d3, bv.y);
        }
    }
#pragma unroll
    for (int i = 0; i < 4; i++) {
        float4 o;
        unpack2(o.x, o.y, acc[i][0]);
        unpack2(o.z, o.w, acc[i][1]);
        int row = y*64 + 4*ty + i;
        *reinterpret_cast<float4*>(
            &g_part[((size_t)kc * 1024 + row) * 128 + eo0 + 4*tx]) = o;
    }
}

// ---------------- K5b: reduce split-K partials + bias ---------------------
__global__ void __launch_bounds__(256) k_red(const float* __restrict__ bout,
                                             float* __restrict__ out)
{
    int i4 = blockIdx.x * 256 + threadIdx.x;        // float4 index, < 32768
    const float4* P = reinterpret_cast<const float4*>(g_part);
    float4 s = P[i4];
#pragma unroll
    for (int k = 1; k < 8; k++) {
        float4 v = P[(size_t)k * 32768 + i4];
        s.x += v.x; s.y += v.y; s.z += v.z; s.w += v.w;
    }
    float4 bo = reinterpret_cast<const float4*>(bout)[i4 & 31];
    s.x += bo.x; s.y += bo.y; s.z += bo.z; s.w += bo.w;
    reinterpret_cast<float4*>(out)[i4] = s;
}

// ---------------- K6: finalize affinity / prmsd ---------------------------
__global__ void k_fin(const float* __restrict__ bias,
                      const float* __restrict__ bias_p,
                      float* __restrict__ out)
{
    int t = threadIdx.x;
    if (t < 4) {
        float a = bias[0] + g_acc[t];
        out[131072 + t] = (a > 0.f) ? a : 0.01f * a;
        float p = bias_p[0] + g_acc[4 + t];
        out[131076 + t] = (p > 0.f) ? p : 0.01f * p;
    }
}

// ---------------- launch --------------------------------------------------
extern "C" void kernel_launch(void* const* d_in, const int* in_sizes, int n_in,
                              void* d_out, int out_size)
{
    const float* z      = (const float*)d_in[0];
    const void*  zmask  = d_in[1];
    const float* pocket = (const float*)d_in[2];
    const float* cand   = (const float*)d_in[3];
    const float* Wlin   = (const float*)d_in[4];
    const float* blin   = (const float*)d_in[5];
    const float* Wdis   = (const float*)d_in[6];
    const float* bdis   = (const float*)d_in[7];
    const float* We     = (const float*)d_in[8];
    const float* be     = (const float*)d_in[9];
    const float* Wg     = (const float*)d_in[10];
    const float* bg     = (const float*)d_in[11];
    const float* bias   = (const float*)d_in[12];
    const float* Wep    = (const float*)d_in[13];
    const float* bep    = (const float*)d_in[14];
    const float* Wgp    = (const float*)d_in[15];
    const float* bgp    = (const float*)d_in[16];
    const float* biasp  = (const float*)d_in[17];
    const float* Wout   = (const float*)d_in[18];
    const float* bout   = (const float*)d_in[19];
    float* out = (float*)d_out;

    const int K1_SMEM = 29984 * 4;    // 119936 bytes
    const int KO_SMEM = 16384 * 4;    // 65536 bytes
    cudaFuncSetAttribute(k_main, cudaFuncAttributeMaxDynamicSharedMemorySize, K1_SMEM);
    cudaFuncSetAttribute(k_out,  cudaFuncAttributeMaxDynamicSharedMemorySize, KO_SMEM);

    k_detect<<<1, 32>>>((const unsigned int*)zmask);
    k_disb<<<(B_*NP_*NC_)/8, 256>>>(cand, Wdis, bdis);
    k_main<<<B_*NC_, 512, K1_SMEM>>>(z, zmask, pocket, Wlin, blin,
                                     We, be, Wg, bg, Wep, bep, Wgp, bgp);
    k_out<<<dim3(2, 16, 8), 256, KO_SMEM>>>(Wout);
    k_red<<<128, 256>>>(bout, out);
    k_fin<<<1, 32>>>(bias, biasp, out);
}